// round 6
// baseline (speedup 1.0000x reference)
#include <cuda_runtime.h>
#include <cuda_bf16.h>
#include <math.h>
#include <stdint.h>

#define S_  2048
#define E_  2048
#define H_  16
#define QR_ 512
#define KVR_ 512
#define DR_ 64
#define DV_ 128
#define DQK_ 192   // DV + DR

typedef __nv_bfloat16 bf16;

// ---------------- scratch (device globals) ----------------
__device__ float g_cq [S_ * QR_];
__device__ float g_ckv[S_ * KVR_];
__device__ float g_qc [S_ * (H_*DV_)];
__device__ float g_qr [S_ * (H_*DR_)];
__device__ float g_kv [S_ * (H_*2*DV_)];
__device__ float g_kr [S_ * DR_];
// interleaved tf32 hi/lo splits
__device__ float2 g_x2   [S_*E_];
__device__ float2 g_wqd2 [QR_*E_];
__device__ float2 g_wqu2 [H_*DV_*QR_];
__device__ float2 g_wqr2 [H_*DR_*QR_];
__device__ float2 g_wkvd2[KVR_*E_];
__device__ float2 g_wkvu2[H_*2*DV_*KVR_];
__device__ float2 g_wkr2 [DR_*E_];
__device__ float2 g_cq2  [S_*QR_];
__device__ float2 g_ckv2 [S_*KVR_];
// bf16 split of wo
__device__ bf16 g_wo_h[E_*H_*DV_], g_wo_l[E_*H_*DV_];
// attention tensors
__device__ bf16 g_q[(size_t)H_ * S_ * DQK_];
__device__ bf16 g_k[(size_t)H_ * S_ * DQK_];
__device__ bf16 g_v[(size_t)H_ * S_ * DV_];
__device__ bf16 g_vT[(size_t)H_ * DV_ * S_];
__device__ bf16 g_logits[(size_t)H_ * S_ * S_];
__device__ bf16 g_probs [(size_t)H_ * S_ * S_];
__device__ bf16 g_attn_bf[(size_t)S_ * H_ * DV_];

// ---------------- helpers ----------------
__device__ __forceinline__ uint32_t f2tf32(float x) {
    uint32_t r;
    asm("cvt.rna.tf32.f32 %0, %1;" : "=r"(r) : "f"(x));
    return r;
}

#define MMA_TF32(c, a, b) \
    asm volatile( \
        "mma.sync.aligned.m16n8k8.row.col.f32.tf32.tf32.f32 " \
        "{%0,%1,%2,%3}, {%4,%5,%6,%7}, {%8,%9}, {%0,%1,%2,%3};" \
        : "+f"((c)[0]), "+f"((c)[1]), "+f"((c)[2]), "+f"((c)[3]) \
        : "r"((a)[0]), "r"((a)[1]), "r"((a)[2]), "r"((a)[3]), \
          "r"((b)[0]), "r"((b)[1]))

#define MMA_BF16(c, a, b) \
    asm volatile( \
        "mma.sync.aligned.m16n8k16.row.col.f32.bf16.bf16.f32 " \
        "{%0,%1,%2,%3}, {%4,%5,%6,%7}, {%8,%9}, {%0,%1,%2,%3};" \
        : "+f"((c)[0]), "+f"((c)[1]), "+f"((c)[2]), "+f"((c)[3]) \
        : "r"((a)[0]), "r"((a)[1]), "r"((a)[2]), "r"((a)[3]), \
          "r"((b)[0]), "r"((b)[1]))

#define CP16(dst, src, nbytes) \
    asm volatile("cp.async.cg.shared.global [%0], [%1], 16, %2;" \
                 :: "r"(dst), "l"(src), "r"(nbytes))
#define CP_COMMIT()  asm volatile("cp.async.commit_group;")
#define CP_WAIT0()   asm volatile("cp.async.wait_group 0;")

// ---------------- split kernels ----------------
__global__ void split_tf32_k(const float* __restrict__ src, float2* __restrict__ dst, long n)
{
    long i = (long)blockIdx.x * blockDim.x + threadIdx.x;
    long stride = (long)gridDim.x * blockDim.x;
    for (; i < n; i += stride) {
        float v = src[i];
        uint32_t h = f2tf32(v);
        uint32_t l = f2tf32(v - __uint_as_float(h));
        dst[i] = make_float2(__uint_as_float(h), __uint_as_float(l));
    }
}

__global__ void split_bf_k(const float* __restrict__ src, bf16* __restrict__ hi,
                           bf16* __restrict__ lo, long n)
{
    long i = (long)blockIdx.x * blockDim.x + threadIdx.x;
    long stride = (long)gridDim.x * blockDim.x;
    for (; i < n; i += stride) {
        float v = src[i];
        bf16 h = __float2bfloat16(v);
        hi[i] = h;
        lo[i] = __float2bfloat16(v - __bfloat162float(h));
    }
}

// ============================================================================
// 3xTF32 GEMM on precomputed interleaved hi/lo (float2) operands.
// Chunked-IEEE accumulation (chain of 6 mma per K-tile from zero fragment,
// then IEEE FADD). cp.async double-buffered. Dynamic smem = 72 KB.
// ============================================================================
#define FBM 128
#define FBN 128
#define FBK 16
#define SROW 36      // floats per smem row (32 data + 4 pad)

__global__ __launch_bounds__(256)
void tf32_gemm(const float2* __restrict__ A2, const float2* __restrict__ B2,
               float* __restrict__ C, int M, int N, int K,
               long lda, long ldb, long ldc)
{
    extern __shared__ float dsm[];
    float* sA = dsm;                        // [2][128*SROW]
    float* sB = dsm + 2 * FBM * SROW;       // [2][128*SROW]

    const int m0 = blockIdx.y * FBM;
    const int n0 = blockIdx.x * FBN;
    const int tid = threadIdx.x;
    const int warp = tid >> 5;
    const int lane = tid & 31;
    const int gid = lane >> 2;
    const int tig = lane & 3;
    const int wm = (warp >> 1) * 32;
    const int wn = (warp & 1) * 64;

    // per-thread load descriptors: 4 chunks (16B = 2 float2) each for A and B
    const float2* aSrc[4];
    const float2* bSrc[4];
    uint32_t sOff[4];
    int bPred[4];
    const uint32_t saBase = (uint32_t)__cvta_generic_to_shared(sA);
    const uint32_t sbBase = (uint32_t)__cvta_generic_to_shared(sB);
#pragma unroll
    for (int it = 0; it < 4; it++) {
        int idx = tid + it * 256;          // 0..1023
        int row = idx >> 3, ch = idx & 7;  // 128 rows x 8 chunks
        aSrc[it] = A2 + (long)(m0 + row) * lda + ch * 2;
        int nrow = n0 + row;
        bPred[it] = (nrow < N) ? 16 : 0;
        if (nrow >= N) nrow = N - 1;
        bSrc[it] = B2 + (long)nrow * ldb + ch * 2;
        sOff[it] = (uint32_t)(row * SROW + ch * 4) * 4u;  // bytes
    }
    const uint32_t ABUF = FBM * SROW * 4u;

    float acc[2][8][4];
#pragma unroll
    for (int mt = 0; mt < 2; mt++)
#pragma unroll
        for (int nt = 0; nt < 8; nt++)
#pragma unroll
            for (int r = 0; r < 4; r++) acc[mt][nt][r] = 0.f;

    const int NT = K / FBK;

    // prologue: tile 0 -> buf 0
#pragma unroll
    for (int it = 0; it < 4; it++) {
        CP16(saBase + sOff[it], aSrc[it], 16);
        CP16(sbBase + sOff[it], bSrc[it], bPred[it]);
    }
    CP_COMMIT();

    for (int t = 0; t < NT; t++) {
        const int cur = t & 1;
        CP_WAIT0();
        __syncthreads();

        if (t + 1 < NT) {
            const long kk = (long)(t + 1) * FBK;   // in float2 units
            const uint32_t bo = (cur ^ 1) * ABUF;
#pragma unroll
            for (int it = 0; it < 4; it++) {
                CP16(saBase + bo + sOff[it], aSrc[it] + kk, 16);
                CP16(sbBase + bo + sOff[it], bSrc[it] + kk, bPred[it]);
            }
            CP_COMMIT();
        }

        const float* cA = sA + cur * FBM * SROW;
        const float* cB = sB + cur * FBM * SROW;

        uint32_t ah[2][2][4], al[2][2][4];
#pragma unroll
        for (int ks = 0; ks < 2; ks++)
#pragma unroll
            for (int mt = 0; mt < 2; mt++)
#pragma unroll
                for (int r = 0; r < 4; r++) {
                    int row = wm + mt * 16 + gid + (r & 1) * 8;
                    int col = ks * 8 + tig + (r >> 1) * 4;
                    float2 v = *(const float2*)&cA[row * SROW + col * 2];
                    ah[ks][mt][r] = __float_as_uint(v.x);
                    al[ks][mt][r] = __float_as_uint(v.y);
                }

#pragma unroll
        for (int nt = 0; nt < 8; nt++) {
            uint32_t bh[2][2], bl[2][2];
#pragma unroll
            for (int ks = 0; ks < 2; ks++)
#pragma unroll
                for (int r = 0; r < 2; r++) {
                    int n = wn + nt * 8 + gid;
                    int kq = ks * 8 + tig + r * 4;
                    float2 v = *(const float2*)&cB[n * SROW + kq * 2];
                    bh[ks][r] = __float_as_uint(v.x);
                    bl[ks][r] = __float_as_uint(v.y);
                }
#pragma unroll
            for (int mt = 0; mt < 2; mt++) {
                float f[4] = {0.f, 0.f, 0.f, 0.f};
#pragma unroll
                for (int ks = 0; ks < 2; ks++) {
                    MMA_TF32(f, ah[ks][mt], bh[ks]);
                    MMA_TF32(f, ah[ks][mt], bl[ks]);
                    MMA_TF32(f, al[ks][mt], bh[ks]);
                }
                float* c = acc[mt][nt];
                c[0] += f[0]; c[1] += f[1]; c[2] += f[2]; c[3] += f[3];
            }
        }
    }

#pragma unroll
    for (int mt = 0; mt < 2; mt++) {
        int row0 = m0 + wm + mt * 16 + gid;
#pragma unroll
        for (int nt = 0; nt < 8; nt++) {
            int n = n0 + wn + nt * 8 + tig * 2;
            if (n >= N) continue;
            float* c = acc[mt][nt];
            C[(long)row0 * ldc + n]         = c[0];
            C[(long)row0 * ldc + n + 1]     = c[1];
            C[(long)(row0+8) * ldc + n]     = c[2];
            C[(long)(row0+8) * ldc + n + 1] = c[3];
        }
    }
}

// ============================================================================
// bf16 tensor-core GEMM, chunked-IEEE accumulation, cp.async double-buffered,
// multi-pass (npass operand pairs accumulated in fp32).
// ============================================================================
#define TBM 128
#define TBN 128
#define TBK 32
#define PADK 40

template <typename TC>
__global__ __launch_bounds__(256)
void bf16_gemm(const bf16* __restrict__ A0, const bf16* __restrict__ A1,
               const bf16* __restrict__ B0, const bf16* __restrict__ B1,
               TC* __restrict__ C, int npass, int M, int N, int K,
               long lda, long ldb, long ldc, long Abat, long Bbat, long Cbat)
{
    __shared__ bf16 sA[2][TBM * PADK];
    __shared__ bf16 sB[2][TBN * PADK];

    const long zo = blockIdx.z;
    C += zo * Cbat;

    const int m0 = blockIdx.y * TBM;
    const int n0 = blockIdx.x * TBN;
    const int tid = threadIdx.x;
    const int warp = tid >> 5;
    const int lane = tid & 31;
    const int gid = lane >> 2;
    const int tig = lane & 3;
    const int wm = (warp >> 1) * 32;
    const int wn = (warp & 1) * 64;

    const uint32_t saBase = (uint32_t)__cvta_generic_to_shared(sA);
    const uint32_t sbBase = (uint32_t)__cvta_generic_to_shared(sB);
    const uint32_t ABUF = TBM * PADK * 2u;

    float acc[2][8][4];
#pragma unroll
    for (int mt = 0; mt < 2; mt++)
#pragma unroll
        for (int nt = 0; nt < 8; nt++)
#pragma unroll
            for (int r = 0; r < 4; r++) acc[mt][nt][r] = 0.f;

    const int NT = K / TBK;

    for (int p = 0; p < npass; p++) {
        const bf16* A = (p ? A1 : A0) + zo * Abat;
        const bf16* B = (p ? B1 : B0) + zo * Bbat;

        const bf16* aSrc[2];
        const bf16* bSrc[2];
        uint32_t sOff[2];
        int bPred[2];
#pragma unroll
        for (int it = 0; it < 2; it++) {
            int idx = tid + it * 256;
            int row = idx >> 2, ch = idx & 3;
            aSrc[it] = A + (long)(m0 + row) * lda + ch * 8;
            int nrow = n0 + row;
            bPred[it] = (nrow < N) ? 16 : 0;
            if (nrow >= N) nrow = N - 1;
            bSrc[it] = B + (long)nrow * ldb + ch * 8;
            sOff[it] = (uint32_t)(row * PADK + ch * 8) * 2u;
        }

        if (p) __syncthreads();   // previous pass fully done before buf reuse

#pragma unroll
        for (int it = 0; it < 2; it++) {
            CP16(saBase + sOff[it], aSrc[it], 16);
            CP16(sbBase + sOff[it], bSrc[it], bPred[it]);
        }
        CP_COMMIT();

        for (int t = 0; t < NT; t++) {
            const int cur = t & 1;
            CP_WAIT0();
            __syncthreads();

            if (t + 1 < NT) {
                const long kk = (long)(t + 1) * TBK;
                const uint32_t bo = (cur ^ 1) * ABUF;
#pragma unroll
                for (int it = 0; it < 2; it++) {
                    CP16(saBase + bo + sOff[it], aSrc[it] + kk, 16);
                    CP16(sbBase + bo + sOff[it], bSrc[it] + kk, bPred[it]);
                }
                CP_COMMIT();
            }

            const bf16* cA = sA[cur];
            const bf16* cB = sB[cur];

            uint32_t a[2][2][4];   // [ks][mt][reg]
#pragma unroll
            for (int ks = 0; ks < 2; ks++)
#pragma unroll
                for (int mt = 0; mt < 2; mt++)
#pragma unroll
                    for (int r = 0; r < 4; r++) {
                        int row = wm + mt * 16 + gid + (r & 1) * 8;
                        int col = ks * 16 + tig * 2 + (r >> 1) * 8;
                        a[ks][mt][r] = *(const uint32_t*)&cA[row * PADK + col];
                    }

#pragma unroll
            for (int nt = 0; nt < 8; nt++) {
                uint32_t b[2][2];
#pragma unroll
                for (int ks = 0; ks < 2; ks++)
#pragma unroll
                    for (int r = 0; r < 2; r++) {
                        int n  = wn + nt * 8 + gid;
                        int kq = ks * 16 + tig * 2 + r * 8;
                        b[ks][r] = *(const uint32_t*)&cB[n * PADK + kq];
                    }
#pragma unroll
                for (int mt = 0; mt < 2; mt++) {
                    float f[4] = {0.f, 0.f, 0.f, 0.f};
                    MMA_BF16(f, a[0][mt], b[0]);
                    MMA_BF16(f, a[1][mt], b[1]);
                    float* c = acc[mt][nt];
                    c[0] += f[0]; c[1] += f[1]; c[2] += f[2]; c[3] += f[3];
                }
            }
        }
    }

#pragma unroll
    for (int mt = 0; mt < 2; mt++) {
        int row0 = m0 + wm + mt * 16 + gid;
#pragma unroll
        for (int nt = 0; nt < 8; nt++) {
            int n = n0 + wn + nt * 8 + tig * 2;
            if (n >= N) continue;
            float* c = acc[mt][nt];
            if (sizeof(TC) == 4) {
                float* Cf = (float*)C;
                Cf[(long)row0 * ldc + n]         = c[0];
                Cf[(long)row0 * ldc + n + 1]     = c[1];
                Cf[(long)(row0+8) * ldc + n]     = c[2];
                Cf[(long)(row0+8) * ldc + n + 1] = c[3];
            } else {
                bf16* Cb = (bf16*)C;
                *(__nv_bfloat162*)&Cb[(long)row0 * ldc + n] =
                    __nv_bfloat162(__float2bfloat16(c[0]), __float2bfloat16(c[1]));
                *(__nv_bfloat162*)&Cb[(long)(row0+8) * ldc + n] =
                    __nv_bfloat162(__float2bfloat16(c[2]), __float2bfloat16(c[3]));
            }
        }
    }
}

// ---------------- pack q/k/v (bf16, head-major) + RoPE ----------------
__global__ void pack_k(const float* __restrict__ qc, const float* __restrict__ qr,
                       const float* __restrict__ kv, const float* __restrict__ kr,
                       bf16* __restrict__ q, bf16* __restrict__ k, bf16* __restrict__ v)
{
    const int s = blockIdx.x;
    const int tid = threadIdx.x;  // 256

    __shared__ float ssin[32], scos[32];
    if (tid < 32) {
        double invf_d = pow(10000.0, -((double)(2 * tid)) / 64.0);
        float invf = (float)invf_d;
        float ang = (float)s * invf;
        double a = (double)ang;
        ssin[tid] = (float)sin(a);
        scos[tid] = (float)cos(a);
    }
    __syncthreads();

    for (int idx = tid; idx < H_ * DV_; idx += 256) {
        int h = idx >> 7, d = idx & 127;
        q[((long)h * S_ + s) * DQK_ + d] = __float2bfloat16(qc[(long)s * (H_*DV_) + idx]);
        k[((long)h * S_ + s) * DQK_ + d] = __float2bfloat16(kv[(long)s * (H_*2*DV_) + idx]);
        v[((long)h * S_ + s) * DV_ + d]  = __float2bfloat16(kv[(long)s * (H_*2*DV_) + H_*DV_ + idx]);
    }

    for (int idx = tid; idx < H_ * 32; idx += 256) {
        int h = idx >> 5, j = idx & 31;
        float x1 = qr[(long)s * (H_*DR_) + h * DR_ + j];
        float x2 = qr[(long)s * (H_*DR_) + h * DR_ + 32 + j];
        float sn = ssin[j], cs = scos[j];
        q[((long)h * S_ + s) * DQK_ + DV_ + j]      = __float2bfloat16(x1 * cs - x2 * sn);
        q[((long)h * S_ + s) * DQK_ + DV_ + 32 + j] = __float2bfloat16(x2 * cs + x1 * sn);
    }

    if (tid < 32) {
        int j = tid;
        float x1 = kr[(long)s * DR_ + j];
        float x2 = kr[(long)s * DR_ + 32 + j];
        float sn = ssin[j], cs = scos[j];
        float r1 = x1 * cs - x2 * sn;
        float r2 = x2 * cs + x1 * sn;
#pragma unroll
        for (int h = 0; h < H_; h++) {
            k[((long)h * S_ + s) * DQK_ + DV_ + j]      = __float2bfloat16(r1);
            k[((long)h * S_ + s) * DQK_ + DV_ + 32 + j] = __float2bfloat16(r2);
        }
    }
}

// ---------------- transpose v [h][s][d] -> vT [h][d][s] ----------------
__global__ void transpose_v(const bf16* __restrict__ v, bf16* __restrict__ vT)
{
    __shared__ bf16 t[32][33];
    const int h = blockIdx.z;
    const int s0 = blockIdx.x * 32;
    const int d0 = blockIdx.y * 32;
    const int tx = threadIdx.x, ty = threadIdx.y;  // (32, 8)
#pragma unroll
    for (int j = 0; j < 32; j += 8)
        t[ty + j][tx] = v[((long)h * S_ + s0 + ty + j) * DV_ + d0 + tx];
    __syncthreads();
#pragma unroll
    for (int j = 0; j < 32; j += 8)
        vT[((long)h * DV_ + d0 + ty + j) * S_ + s0 + tx] = t[tx][ty + j];
}

// ---------------- softmax over bf16 logits -> bf16 probs ----------------
__global__ void softmax_k(const bf16* __restrict__ L, bf16* __restrict__ P, float scale)
{
    const int s = blockIdx.x;
    const int h = blockIdx.y;
    const bf16* row = L + ((long)h * S_ + s) * S_;
    bf16* prow = P + ((long)h * S_ + s) * S_;
    const int tid = threadIdx.x;  // 256, 8 elems each

    float v[8];
    float mx = -1e30f;
#pragma unroll
    for (int i = 0; i < 8; i++) {
        v[i] = __bfloat162float(row[tid + i * 256]) * scale;
        mx = fmaxf(mx, v[i]);
    }
    __shared__ float red[256];
    red[tid] = mx;
    __syncthreads();
    for (int st = 128; st > 0; st >>= 1) {
        if (tid < st) red[tid] = fmaxf(red[tid], red[tid + st]);
        __syncthreads();
    }
    mx = red[0];
    __syncthreads();

    float sum = 0.f;
#pragma unroll
    for (int i = 0; i < 8; i++) {
        v[i] = expf(v[i] - mx);
        sum += v[i];
    }
    red[tid] = sum;
    __syncthreads();
    for (int st = 128; st > 0; st >>= 1) {
        if (tid < st) red[tid] += red[tid + st];
        __syncthreads();
    }
    float tot = red[0];
#pragma unroll
    for (int i = 0; i < 8; i++)
        prow[tid + i * 256] = __float2bfloat16(v[i] / tot);
}

// ---------------- orchestration ----------------
extern "C" void kernel_launch(void* const* d_in, const int* in_sizes, int n_in,
                              void* d_out, int out_size)
{
    (void)in_sizes; (void)n_in; (void)out_size;
    const float* x       = (const float*)d_in[0];
    const float* wq_down = (const float*)d_in[1];
    const float* wq_up   = (const float*)d_in[2];
    const float* wq_rope = (const float*)d_in[3];
    const float* wkv_down= (const float*)d_in[4];
    const float* wkv_up  = (const float*)d_in[5];
    const float* wk_rope = (const float*)d_in[6];
    const float* wo      = (const float*)d_in[7];
    float* out = (float*)d_out;

    float *cq, *ckv, *qc, *qr, *kvf, *kr;
    cudaGetSymbolAddress((void**)&cq,  g_cq);
    cudaGetSymbolAddress((void**)&ckv, g_ckv);
    cudaGetSymbolAddress((void**)&qc,  g_qc);
    cudaGetSymbolAddress((void**)&qr,  g_qr);
    cudaGetSymbolAddress((void**)&kvf, g_kv);
    cudaGetSymbolAddress((void**)&kr,  g_kr);

    float2 *x2, *wqd2, *wqu2, *wqr2, *wkvd2, *wkvu2, *wkr2, *cq2, *ckv2;
    cudaGetSymbolAddress((void**)&x2,    g_x2);
    cudaGetSymbolAddress((void**)&wqd2,  g_wqd2);
    cudaGetSymbolAddress((void**)&wqu2,  g_wqu2);
    cudaGetSymbolAddress((void**)&wqr2,  g_wqr2);
    cudaGetSymbolAddress((void**)&wkvd2, g_wkvd2);
    cudaGetSymbolAddress((void**)&wkvu2, g_wkvu2);
    cudaGetSymbolAddress((void**)&wkr2,  g_wkr2);
    cudaGetSymbolAddress((void**)&cq2,   g_cq2);
    cudaGetSymbolAddress((void**)&ckv2,  g_ckv2);

    bf16 *q, *k, *v, *vT, *logits, *probs, *attn_bf, *wo_h, *wo_l;
    cudaGetSymbolAddress((void**)&q, g_q);
    cudaGetSymbolAddress((void**)&k, g_k);
    cudaGetSymbolAddress((void**)&v, g_v);
    cudaGetSymbolAddress((void**)&vT, g_vT);
    cudaGetSymbolAddress((void**)&logits, g_logits);
    cudaGetSymbolAddress((void**)&probs, g_probs);
    cudaGetSymbolAddress((void**)&attn_bf, g_attn_bf);
    cudaGetSymbolAddress((void**)&wo_h, g_wo_h);
    cudaGetSymbolAddress((void**)&wo_l, g_wo_l);

    const int TF32_SMEM = 2 * 2 * FBM * SROW * 4;  // 73728 B
    cudaFuncSetAttribute(tf32_gemm, cudaFuncAttributeMaxDynamicSharedMemorySize, TF32_SMEM);

    dim3 blk(256);
    auto fgrid = [](int M, int N) {
        return dim3((N + FBN - 1) / FBN, (M + FBM - 1) / FBM, 1);
    };
    auto bgrid = [](int M, int N, int batch) {
        return dim3((N + TBN - 1) / TBN, (M + TBM - 1) / TBM, batch);
    };
    auto splitf = [&](const float* src, float2* dst, long n) {
        split_tf32_k<<<592, 256>>>(src, dst, n);
    };

    // 0) precompute tf32 hi/lo interleaved splits
    splitf(x,        x2,    (long)S_*E_);
    splitf(wq_down,  wqd2,  (long)QR_*E_);
    splitf(wkv_down, wkvd2, (long)KVR_*E_);
    splitf(wk_rope,  wkr2,  (long)DR_*E_);
    splitf(wq_up,    wqu2,  (long)H_*DV_*QR_);
    splitf(wq_rope,  wqr2,  (long)H_*DR_*QR_);
    splitf(wkv_up,   wkvu2, (long)H_*2*DV_*KVR_);
    split_bf_k<<<592, 256>>>(wo, wo_h, wo_l, (long)E_*H_*DV_);

    // 1) down projections (3xTF32, chunked-IEEE ~ fp32)
    tf32_gemm<<<fgrid(S_, QR_), blk, TF32_SMEM>>>(x2, wqd2, cq, S_, QR_, E_, E_, E_, QR_);
    tf32_gemm<<<fgrid(S_, KVR_), blk, TF32_SMEM>>>(x2, wkvd2, ckv, S_, KVR_, E_, E_, E_, KVR_);
    tf32_gemm<<<fgrid(S_, DR_), blk, TF32_SMEM>>>(x2, wkr2, kr, S_, DR_, E_, E_, E_, DR_);

    // 2) split latents, up projections
    splitf(cq,  cq2,  (long)S_*QR_);
    splitf(ckv, ckv2, (long)S_*KVR_);
    tf32_gemm<<<fgrid(S_, H_*DV_), blk, TF32_SMEM>>>(cq2, wqu2, qc, S_, H_*DV_, QR_, QR_, QR_, H_*DV_);
    tf32_gemm<<<fgrid(S_, H_*DR_), blk, TF32_SMEM>>>(cq2, wqr2, qr, S_, H_*DR_, QR_, QR_, QR_, H_*DR_);
    tf32_gemm<<<fgrid(S_, H_*2*DV_), blk, TF32_SMEM>>>(ckv2, wkvu2, kvf, S_, H_*2*DV_, KVR_, KVR_, KVR_, H_*2*DV_);

    // 3) pack + rope -> head-major bf16 q/k/v ; transpose v
    pack_k<<<S_, 256>>>(qc, qr, kvf, kr, q, k, v);
    {
        dim3 tg(S_/32, DV_/32, H_);
        dim3 tb(32, 8);
        transpose_v<<<tg, tb>>>(v, vT);
    }

    // 4) logits[h] = bf16( q[h] @ k[h]^T )
    bf16_gemm<bf16><<<bgrid(S_, S_, H_), blk>>>(
        q, q, k, k, logits, 1, S_, S_, DQK_, DQK_, DQK_, S_,
        (long)S_*DQK_, (long)S_*DQK_, (long)S_*S_);

    // 5) softmax
    {
        dim3 g(S_, H_);
        softmax_k<<<g, 256>>>(logits, probs, 1.0f / sqrtf((float)(DV_ + DR_)));
    }

    // 6) attn[h] = bf16( probs[h] @ v[h] ), stored bf16 interleaved [s][h*DV]
    bf16_gemm<bf16><<<bgrid(S_, DV_, H_), blk>>>(
        probs, probs, vT, vT, attn_bf, 1, S_, DV_, S_, S_, S_, (long)H_*DV_,
        (long)S_*S_, (long)DV_*S_, DV_);

    // 7) out = attn(bf16-exact) @ wo^T : 2-pass bf16 (wo = hi + lo)
    bf16_gemm<float><<<bgrid(S_, E_, 1), blk>>>(
        attn_bf, attn_bf, wo_h, wo_l, out, 2, S_, E_, H_*DV_,
        H_*DV_, H_*DV_, E_, 0, 0, 0);
}

// round 7
// speedup vs baseline: 1.6424x; 1.6424x over previous
#include <cuda_runtime.h>
#include <cuda_bf16.h>
#include <math.h>
#include <stdint.h>

#define S_  2048
#define E_  2048
#define H_  16
#define QR_ 512
#define KVR_ 512
#define DR_ 64
#define DV_ 128
#define DQK_ 192   // DV + DR
#define NDWN 1088  // QR + KVR + DR
#define NQU  3072  // H*DV + H*DR

typedef __nv_bfloat16 bf16;

// ---------------- scratch (device globals) ----------------
__device__ float g_wd [NDWN * E_];          // concat [wq_down; wkv_down; wk_rope]
__device__ float g_wu [NQU * QR_];          // concat [wq_up; wq_rope]
__device__ float g_down[S_ * NDWN];         // [cq | ckv | kr] per row
__device__ float g_qu [S_ * NQU];           // [qc | qr] per row
__device__ float g_kv [S_ * (H_*2*DV_)];
__device__ bf16 g_wo_h[E_*H_*DV_], g_wo_l[E_*H_*DV_];
__device__ bf16 g_q[(size_t)H_ * S_ * DQK_];
__device__ bf16 g_k[(size_t)H_ * S_ * DQK_];
__device__ bf16 g_v[(size_t)H_ * S_ * DV_];
__device__ bf16 g_vT[(size_t)H_ * DV_ * S_];
__device__ bf16 g_logits[(size_t)H_ * S_ * S_];
__device__ bf16 g_probs [(size_t)H_ * S_ * S_];
__device__ bf16 g_attn_bf[(size_t)S_ * H_ * DV_];

// ---------------- helpers ----------------
__device__ __forceinline__ uint32_t f2tf32(float x) {
    uint32_t r;
    asm("cvt.rna.tf32.f32 %0, %1;" : "=r"(r) : "f"(x));
    return r;
}

#define MMA_TF32(c, a, b) \
    asm volatile( \
        "mma.sync.aligned.m16n8k8.row.col.f32.tf32.tf32.f32 " \
        "{%0,%1,%2,%3}, {%4,%5,%6,%7}, {%8,%9}, {%0,%1,%2,%3};" \
        : "+f"((c)[0]), "+f"((c)[1]), "+f"((c)[2]), "+f"((c)[3]) \
        : "r"((a)[0]), "r"((a)[1]), "r"((a)[2]), "r"((a)[3]), \
          "r"((b)[0]), "r"((b)[1]))

#define MMA_BF16(c, a, b) \
    asm volatile( \
        "mma.sync.aligned.m16n8k16.row.col.f32.bf16.bf16.f32 " \
        "{%0,%1,%2,%3}, {%4,%5,%6,%7}, {%8,%9}, {%0,%1,%2,%3};" \
        : "+f"((c)[0]), "+f"((c)[1]), "+f"((c)[2]), "+f"((c)[3]) \
        : "r"((a)[0]), "r"((a)[1]), "r"((a)[2]), "r"((a)[3]), \
          "r"((b)[0]), "r"((b)[1]))

#define CP16(dst, src, nbytes) \
    asm volatile("cp.async.cg.shared.global [%0], [%1], 16, %2;" \
                 :: "r"(dst), "l"(src), "r"(nbytes))
#define CP_COMMIT()  asm volatile("cp.async.commit_group;")
#define CP_WAIT0()   asm volatile("cp.async.wait_group 0;")

__global__ void split_bf_k(const float* __restrict__ src, bf16* __restrict__ hi,
                           bf16* __restrict__ lo, long n)
{
    long i = (long)blockIdx.x * blockDim.x + threadIdx.x;
    long stride = (long)gridDim.x * blockDim.x;
    for (; i < n; i += stride) {
        float v = src[i];
        bf16 h = __float2bfloat16(v);
        hi[i] = h;
        lo[i] = __float2bfloat16(v - __bfloat162float(h));
    }
}

// ============================================================================
// 3xTF32 GEMM (R5 version: in-register hi/lo conversion, fp32 smem tiles).
// Chunked-IEEE accumulation. cp.async double-buffered.
// ============================================================================
#define FBM 128
#define FBN 128
#define FBK 16
#define FPAD 20

__global__ __launch_bounds__(256)
void tf32_gemm(const float* __restrict__ A, const float* __restrict__ B,
               float* __restrict__ C, int M, int N, int K,
               long lda, long ldb, long ldc)
{
    __shared__ float sA[2][FBM * FPAD];
    __shared__ float sB[2][FBN * FPAD];

    const int m0 = blockIdx.y * FBM;
    const int n0 = blockIdx.x * FBN;
    const int tid = threadIdx.x;
    const int warp = tid >> 5;
    const int lane = tid & 31;
    const int gid = lane >> 2;
    const int tig = lane & 3;
    const int wm = (warp >> 1) * 32;
    const int wn = (warp & 1) * 64;

    const float* aSrc[2];
    const float* bSrc[2];
    uint32_t sOff[2];
    int bPred[2];
    const uint32_t saBase = (uint32_t)__cvta_generic_to_shared(sA);
    const uint32_t sbBase = (uint32_t)__cvta_generic_to_shared(sB);
#pragma unroll
    for (int it = 0; it < 2; it++) {
        int idx = tid + it * 256;
        int row = idx >> 2, ch = idx & 3;
        aSrc[it] = A + (long)(m0 + row) * lda + ch * 4;
        int nrow = n0 + row;
        bPred[it] = (nrow < N) ? 16 : 0;
        if (nrow >= N) nrow = N - 1;
        bSrc[it] = B + (long)nrow * ldb + ch * 4;
        sOff[it] = (uint32_t)(row * FPAD + ch * 4) * 4u;
    }
    const uint32_t ABUF = FBM * FPAD * 4u;

    float acc[2][8][4];
#pragma unroll
    for (int mt = 0; mt < 2; mt++)
#pragma unroll
        for (int nt = 0; nt < 8; nt++)
#pragma unroll
            for (int r = 0; r < 4; r++) acc[mt][nt][r] = 0.f;

    const int NT = K / FBK;

#pragma unroll
    for (int it = 0; it < 2; it++) {
        CP16(saBase + sOff[it], aSrc[it], 16);
        CP16(sbBase + sOff[it], bSrc[it], bPred[it]);
    }
    CP_COMMIT();

    for (int t = 0; t < NT; t++) {
        const int cur = t & 1;
        CP_WAIT0();
        __syncthreads();

        if (t + 1 < NT) {
            const long kk = (long)(t + 1) * FBK;
            const uint32_t bo = (cur ^ 1) * ABUF;
#pragma unroll
            for (int it = 0; it < 2; it++) {
                CP16(saBase + bo + sOff[it], aSrc[it] + kk, 16);
                CP16(sbBase + bo + sOff[it], bSrc[it] + kk, bPred[it]);
            }
            CP_COMMIT();
        }

        const float* cA = sA[cur];
        const float* cB = sB[cur];

        uint32_t ah[2][2][4], al[2][2][4];
#pragma unroll
        for (int ks = 0; ks < 2; ks++)
#pragma unroll
            for (int mt = 0; mt < 2; mt++)
#pragma unroll
                for (int r = 0; r < 4; r++) {
                    int row = wm + mt * 16 + gid + (r & 1) * 8;
                    int col = ks * 8 + tig + (r >> 1) * 4;
                    float v = cA[row * FPAD + col];
                    uint32_t h = f2tf32(v);
                    ah[ks][mt][r] = h;
                    al[ks][mt][r] = f2tf32(v - __uint_as_float(h));
                }

#pragma unroll
        for (int nt = 0; nt < 8; nt++) {
            uint32_t bh[2][2], bl[2][2];
#pragma unroll
            for (int ks = 0; ks < 2; ks++)
#pragma unroll
                for (int r = 0; r < 2; r++) {
                    int n = wn + nt * 8 + gid;
                    int kq = ks * 8 + tig + r * 4;
                    float v = cB[n * FPAD + kq];
                    uint32_t h = f2tf32(v);
                    bh[ks][r] = h;
                    bl[ks][r] = f2tf32(v - __uint_as_float(h));
                }
#pragma unroll
            for (int mt = 0; mt < 2; mt++) {
                float f[4] = {0.f, 0.f, 0.f, 0.f};
#pragma unroll
                for (int ks = 0; ks < 2; ks++) {
                    MMA_TF32(f, ah[ks][mt], bh[ks]);
                    MMA_TF32(f, ah[ks][mt], bl[ks]);
                    MMA_TF32(f, al[ks][mt], bh[ks]);
                }
                float* c = acc[mt][nt];
                c[0] += f[0]; c[1] += f[1]; c[2] += f[2]; c[3] += f[3];
            }
        }
    }

#pragma unroll
    for (int mt = 0; mt < 2; mt++) {
        int row0 = m0 + wm + mt * 16 + gid;
#pragma unroll
        for (int nt = 0; nt < 8; nt++) {
            int n = n0 + wn + nt * 8 + tig * 2;
            if (n >= N) continue;
            float* c = acc[mt][nt];
            C[(long)row0 * ldc + n]         = c[0];
            C[(long)row0 * ldc + n + 1]     = c[1];
            C[(long)(row0+8) * ldc + n]     = c[2];
            C[(long)(row0+8) * ldc + n + 1] = c[3];
        }
    }
}

// ============================================================================
// bf16 tensor-core GEMM, chunked-IEEE accumulation, cp.async double-buffered,
// multi-pass (npass operand pairs accumulated in fp32).
// ============================================================================
#define TBM 128
#define TBN 128
#define TBK 32
#define PADK 40

template <typename TC>
__global__ __launch_bounds__(256)
void bf16_gemm(const bf16* __restrict__ A0, const bf16* __restrict__ A1,
               const bf16* __restrict__ B0, const bf16* __restrict__ B1,
               TC* __restrict__ C, int npass, int M, int N, int K,
               long lda, long ldb, long ldc, long Abat, long Bbat, long Cbat)
{
    __shared__ bf16 sA[2][TBM * PADK];
    __shared__ bf16 sB[2][TBN * PADK];

    const long zo = blockIdx.z;
    C += zo * Cbat;

    const int m0 = blockIdx.y * TBM;
    const int n0 = blockIdx.x * TBN;
    const int tid = threadIdx.x;
    const int warp = tid >> 5;
    const int lane = tid & 31;
    const int gid = lane >> 2;
    const int tig = lane & 3;
    const int wm = (warp >> 1) * 32;
    const int wn = (warp & 1) * 64;

    const uint32_t saBase = (uint32_t)__cvta_generic_to_shared(sA);
    const uint32_t sbBase = (uint32_t)__cvta_generic_to_shared(sB);
    const uint32_t ABUF = TBM * PADK * 2u;

    float acc[2][8][4];
#pragma unroll
    for (int mt = 0; mt < 2; mt++)
#pragma unroll
        for (int nt = 0; nt < 8; nt++)
#pragma unroll
            for (int r = 0; r < 4; r++) acc[mt][nt][r] = 0.f;

    const int NT = K / TBK;

    for (int p = 0; p < npass; p++) {
        const bf16* A = (p ? A1 : A0) + zo * Abat;
        const bf16* B = (p ? B1 : B0) + zo * Bbat;

        const bf16* aSrc[2];
        const bf16* bSrc[2];
        uint32_t sOff[2];
        int bPred[2];
#pragma unroll
        for (int it = 0; it < 2; it++) {
            int idx = tid + it * 256;
            int row = idx >> 2, ch = idx & 3;
            aSrc[it] = A + (long)(m0 + row) * lda + ch * 8;
            int nrow = n0 + row;
            bPred[it] = (nrow < N) ? 16 : 0;
            if (nrow >= N) nrow = N - 1;
            bSrc[it] = B + (long)nrow * ldb + ch * 8;
            sOff[it] = (uint32_t)(row * PADK + ch * 8) * 2u;
        }

        if (p) __syncthreads();

#pragma unroll
        for (int it = 0; it < 2; it++) {
            CP16(saBase + sOff[it], aSrc[it], 16);
            CP16(sbBase + sOff[it], bSrc[it], bPred[it]);
        }
        CP_COMMIT();

        for (int t = 0; t < NT; t++) {
            const int cur = t & 1;
            CP_WAIT0();
            __syncthreads();

            if (t + 1 < NT) {
                const long kk = (long)(t + 1) * TBK;
                const uint32_t bo = (cur ^ 1) * ABUF;
#pragma unroll
                for (int it = 0; it < 2; it++) {
                    CP16(saBase + bo + sOff[it], aSrc[it] + kk, 16);
                    CP16(sbBase + bo + sOff[it], bSrc[it] + kk, bPred[it]);
                }
                CP_COMMIT();
            }

            const bf16* cA = sA[cur];
            const bf16* cB = sB[cur];

            uint32_t a[2][2][4];
#pragma unroll
            for (int ks = 0; ks < 2; ks++)
#pragma unroll
                for (int mt = 0; mt < 2; mt++)
#pragma unroll
                    for (int r = 0; r < 4; r++) {
                        int row = wm + mt * 16 + gid + (r & 1) * 8;
                        int col = ks * 16 + tig * 2 + (r >> 1) * 8;
                        a[ks][mt][r] = *(const uint32_t*)&cA[row * PADK + col];
                    }

#pragma unroll
            for (int nt = 0; nt < 8; nt++) {
                uint32_t b[2][2];
#pragma unroll
                for (int ks = 0; ks < 2; ks++)
#pragma unroll
                    for (int r = 0; r < 2; r++) {
                        int n  = wn + nt * 8 + gid;
                        int kq = ks * 16 + tig * 2 + r * 8;
                        b[ks][r] = *(const uint32_t*)&cB[n * PADK + kq];
                    }
#pragma unroll
                for (int mt = 0; mt < 2; mt++) {
                    float f[4] = {0.f, 0.f, 0.f, 0.f};
                    MMA_BF16(f, a[0][mt], b[0]);
                    MMA_BF16(f, a[1][mt], b[1]);
                    float* c = acc[mt][nt];
                    c[0] += f[0]; c[1] += f[1]; c[2] += f[2]; c[3] += f[3];
                }
            }
        }
    }

#pragma unroll
    for (int mt = 0; mt < 2; mt++) {
        int row0 = m0 + wm + mt * 16 + gid;
#pragma unroll
        for (int nt = 0; nt < 8; nt++) {
            int n = n0 + wn + nt * 8 + tig * 2;
            if (n >= N) continue;
            float* c = acc[mt][nt];
            if (sizeof(TC) == 4) {
                float* Cf = (float*)C;
                Cf[(long)row0 * ldc + n]         = c[0];
                Cf[(long)row0 * ldc + n + 1]     = c[1];
                Cf[(long)(row0+8) * ldc + n]     = c[2];
                Cf[(long)(row0+8) * ldc + n + 1] = c[3];
            } else {
                bf16* Cb = (bf16*)C;
                *(__nv_bfloat162*)&Cb[(long)row0 * ldc + n] =
                    __nv_bfloat162(__float2bfloat16(c[0]), __float2bfloat16(c[1]));
                *(__nv_bfloat162*)&Cb[(long)(row0+8) * ldc + n] =
                    __nv_bfloat162(__float2bfloat16(c[2]), __float2bfloat16(c[3]));
            }
        }
    }
}

// ---------------- pack q/k/v (bf16, head-major) + RoPE ----------------
// qu: [s][3072] = [qc(2048) | qr(1024)] ; kvf: [s][4096] ; dwn: [s][1088], kr at +1024
__global__ void pack_k(const float* __restrict__ qu, const float* __restrict__ kvf,
                       const float* __restrict__ dwn,
                       bf16* __restrict__ q, bf16* __restrict__ k, bf16* __restrict__ v)
{
    const int s = blockIdx.x;
    const int tid = threadIdx.x;  // 256

    __shared__ float ssin[32], scos[32];
    if (tid < 32) {
        double invf_d = pow(10000.0, -((double)(2 * tid)) / 64.0);
        float invf = (float)invf_d;
        float ang = (float)s * invf;
        double a = (double)ang;
        ssin[tid] = (float)sin(a);
        scos[tid] = (float)cos(a);
    }
    __syncthreads();

    for (int idx = tid; idx < H_ * DV_; idx += 256) {
        int h = idx >> 7, d = idx & 127;
        q[((long)h * S_ + s) * DQK_ + d] = __float2bfloat16(qu[(long)s * NQU + idx]);
        k[((long)h * S_ + s) * DQK_ + d] = __float2bfloat16(kvf[(long)s * (H_*2*DV_) + idx]);
        v[((long)h * S_ + s) * DV_ + d]  = __float2bfloat16(kvf[(long)s * (H_*2*DV_) + H_*DV_ + idx]);
    }

    for (int idx = tid; idx < H_ * 32; idx += 256) {
        int h = idx >> 5, j = idx & 31;
        float x1 = qu[(long)s * NQU + 2048 + h * DR_ + j];
        float x2 = qu[(long)s * NQU + 2048 + h * DR_ + 32 + j];
        float sn = ssin[j], cs = scos[j];
        q[((long)h * S_ + s) * DQK_ + DV_ + j]      = __float2bfloat16(x1 * cs - x2 * sn);
        q[((long)h * S_ + s) * DQK_ + DV_ + 32 + j] = __float2bfloat16(x2 * cs + x1 * sn);
    }

    if (tid < 32) {
        int j = tid;
        float x1 = dwn[(long)s * NDWN + 1024 + j];
        float x2 = dwn[(long)s * NDWN + 1024 + 32 + j];
        float sn = ssin[j], cs = scos[j];
        float r1 = x1 * cs - x2 * sn;
        float r2 = x2 * cs + x1 * sn;
#pragma unroll
        for (int h = 0; h < H_; h++) {
            k[((long)h * S_ + s) * DQK_ + DV_ + j]      = __float2bfloat16(r1);
            k[((long)h * S_ + s) * DQK_ + DV_ + 32 + j] = __float2bfloat16(r2);
        }
    }
}

// ---------------- transpose v [h][s][d] -> vT [h][d][s] ----------------
__global__ void transpose_v(const bf16* __restrict__ v, bf16* __restrict__ vT)
{
    __shared__ bf16 t[32][33];
    const int h = blockIdx.z;
    const int s0 = blockIdx.x * 32;
    const int d0 = blockIdx.y * 32;
    const int tx = threadIdx.x, ty = threadIdx.y;  // (32, 8)
#pragma unroll
    for (int j = 0; j < 32; j += 8)
        t[ty + j][tx] = v[((long)h * S_ + s0 + ty + j) * DV_ + d0 + tx];
    __syncthreads();
#pragma unroll
    for (int j = 0; j < 32; j += 8)
        vT[((long)h * DV_ + d0 + ty + j) * S_ + s0 + tx] = t[tx][ty + j];
}

// ---------------- softmax over bf16 logits -> bf16 probs ----------------
__global__ void softmax_k(const bf16* __restrict__ L, bf16* __restrict__ P, float scale)
{
    const int s = blockIdx.x;
    const int h = blockIdx.y;
    const bf16* row = L + ((long)h * S_ + s) * S_;
    bf16* prow = P + ((long)h * S_ + s) * S_;
    const int tid = threadIdx.x;

    float v[8];
    float mx = -1e30f;
#pragma unroll
    for (int i = 0; i < 8; i++) {
        v[i] = __bfloat162float(row[tid + i * 256]) * scale;
        mx = fmaxf(mx, v[i]);
    }
    __shared__ float red[256];
    red[tid] = mx;
    __syncthreads();
    for (int st = 128; st > 0; st >>= 1) {
        if (tid < st) red[tid] = fmaxf(red[tid], red[tid + st]);
        __syncthreads();
    }
    mx = red[0];
    __syncthreads();

    float sum = 0.f;
#pragma unroll
    for (int i = 0; i < 8; i++) {
        v[i] = expf(v[i] - mx);
        sum += v[i];
    }
    red[tid] = sum;
    __syncthreads();
    for (int st = 128; st > 0; st >>= 1) {
        if (tid < st) red[tid] += red[tid + st];
        __syncthreads();
    }
    float tot = red[0];
#pragma unroll
    for (int i = 0; i < 8; i++)
        prow[tid + i * 256] = __float2bfloat16(v[i] / tot);
}

// ---------------- orchestration ----------------
extern "C" void kernel_launch(void* const* d_in, const int* in_sizes, int n_in,
                              void* d_out, int out_size)
{
    (void)in_sizes; (void)n_in; (void)out_size;
    const float* x       = (const float*)d_in[0];
    const float* wq_down = (const float*)d_in[1];
    const float* wq_up   = (const float*)d_in[2];
    const float* wq_rope = (const float*)d_in[3];
    const float* wkv_down= (const float*)d_in[4];
    const float* wkv_up  = (const float*)d_in[5];
    const float* wk_rope = (const float*)d_in[6];
    const float* wo      = (const float*)d_in[7];
    float* out = (float*)d_out;

    float *wd, *wu, *dwn, *qu, *kvf;
    cudaGetSymbolAddress((void**)&wd,  g_wd);
    cudaGetSymbolAddress((void**)&wu,  g_wu);
    cudaGetSymbolAddress((void**)&dwn, g_down);
    cudaGetSymbolAddress((void**)&qu,  g_qu);
    cudaGetSymbolAddress((void**)&kvf, g_kv);

    bf16 *q, *k, *v, *vT, *logits, *probs, *attn_bf, *wo_h, *wo_l;
    cudaGetSymbolAddress((void**)&q, g_q);
    cudaGetSymbolAddress((void**)&k, g_k);
    cudaGetSymbolAddress((void**)&v, g_v);
    cudaGetSymbolAddress((void**)&vT, g_vT);
    cudaGetSymbolAddress((void**)&logits, g_logits);
    cudaGetSymbolAddress((void**)&probs, g_probs);
    cudaGetSymbolAddress((void**)&attn_bf, g_attn_bf);
    cudaGetSymbolAddress((void**)&wo_h, g_wo_h);
    cudaGetSymbolAddress((void**)&wo_l, g_wo_l);

    dim3 blk(256);
    auto fgrid = [](int M, int N) {
        return dim3((N + FBN - 1) / FBN, (M + FBM - 1) / FBM, 1);
    };
    auto bgrid = [](int M, int N, int batch) {
        return dim3((N + TBN - 1) / TBN, (M + TBM - 1) / TBM, batch);
    };

    // 0) concat weights (D2D, graph-capturable) + wo bf16 split
    cudaMemcpyAsync(wd,                 wq_down,  (size_t)QR_ * E_ * 4, cudaMemcpyDeviceToDevice);
    cudaMemcpyAsync(wd + (size_t)QR_*E_, wkv_down, (size_t)KVR_ * E_ * 4, cudaMemcpyDeviceToDevice);
    cudaMemcpyAsync(wd + (size_t)(QR_+KVR_)*E_, wk_rope, (size_t)DR_ * E_ * 4, cudaMemcpyDeviceToDevice);
    cudaMemcpyAsync(wu,                  wq_up,   (size_t)H_*DV_ * QR_ * 4, cudaMemcpyDeviceToDevice);
    cudaMemcpyAsync(wu + (size_t)H_*DV_*QR_, wq_rope, (size_t)H_*DR_ * QR_ * 4, cudaMemcpyDeviceToDevice);
    split_bf_k<<<592, 256>>>(wo, wo_h, wo_l, (long)E_*H_*DV_);

    // 1) fused down projection: [cq|ckv|kr] = x @ wd^T   (N=1088)
    tf32_gemm<<<fgrid(S_, NDWN), blk>>>(x, wd, dwn, S_, NDWN, E_, E_, E_, NDWN);

    // 2) fused q up projection: [qc|qr] = cq @ wu^T  (A = dwn cols 0..511, lda=1088)
    tf32_gemm<<<fgrid(S_, NQU), blk>>>(dwn, wu, qu, S_, NQU, QR_, NDWN, QR_, NQU);
    // kv up: ckv @ wkv_up^T  (A = dwn cols 512..1023)
    tf32_gemm<<<fgrid(S_, H_*2*DV_), blk>>>(dwn + QR_, wkv_up, kvf, S_, H_*2*DV_, KVR_,
                                            NDWN, KVR_, H_*2*DV_);

    // 3) pack + rope -> head-major bf16 q/k/v ; transpose v
    pack_k<<<S_, 256>>>(qu, kvf, dwn, q, k, v);
    {
        dim3 tg(S_/32, DV_/32, H_);
        dim3 tb(32, 8);
        transpose_v<<<tg, tb>>>(v, vT);
    }

    // 4) logits[h] = bf16( q[h] @ k[h]^T )
    bf16_gemm<bf16><<<bgrid(S_, S_, H_), blk>>>(
        q, q, k, k, logits, 1, S_, S_, DQK_, DQK_, DQK_, S_,
        (long)S_*DQK_, (long)S_*DQK_, (long)S_*S_);

    // 5) softmax
    {
        dim3 g(S_, H_);
        softmax_k<<<g, 256>>>(logits, probs, 1.0f / sqrtf((float)(DV_ + DR_)));
    }

    // 6) attn[h] = bf16( probs[h] @ v[h] ), stored bf16 interleaved [s][h*DV]
    bf16_gemm<bf16><<<bgrid(S_, DV_, H_), blk>>>(
        probs, probs, vT, vT, attn_bf, 1, S_, DV_, S_, S_, S_, (long)H_*DV_,
        (long)S_*S_, (long)DV_*S_, DV_);

    // 7) out = attn(bf16-exact) @ wo^T : 2-pass bf16 (wo = hi + lo)
    bf16_gemm<float><<<bgrid(S_, E_, 1), blk>>>(
        attn_bf, attn_bf, wo_h, wo_l, out, 2, S_, E_, H_*DV_,
        H_*DV_, H_*DV_, E_, 0, 0, 0);
}